// round 16
// baseline (speedup 1.0000x reference)
#include <cuda_runtime.h>
#include <cuda_bf16.h>
#include <math.h>

#define BATCH 32
#define HW    512
#define NPIX  (HW*HW)            // 262144
#define WPR   16                 // 32-bit words per row
#define G4PB  (NPIX/4)           // 65536 float4 groups per batch
#define NTHR  254

#define ROWS  16                 // rows per strip
#define NSTR  (HW/ROWS)          // 32 strips
#define HALO  (ROWS+4)           // 20
#define NLW   (HALO*WPR)         // 320 halo words
#define NGH   (HALO*128)         // 2560 halo float4-groups
#define SW    (ROWS*WPR)         // 256 strip words (== blockDim)
#define CAP   (SW*8)             // 2048 staged entries max

// ---------------- device scratch (overwrite-style; counters self-reset via wrap) ----------------
__device__ unsigned g_h2p [BATCH][NSTR][512];    // combined hist partials: bin=2j+hi
__device__ float    g_cpp [BATCH][NSTR][256];    // class-bin sum(p) partials
__device__ float    g_p2p [BATCH][NSTR];         // sum(p^2) partials
__device__ unsigned g_cntp[BATCH][NSTR];         // mask-count partials
__device__ float    g_lossper[BATCH];
__device__ int      g_validb[BATCH];
__device__ unsigned g_done1[BATCH];              // wraps 0..NSTR-1
__device__ unsigned g_done3;                     // wraps 0..BATCH-1

// ======== single kernel: strips + elected per-batch (merge+scan+search+loss) + final scalar ========
__global__ __launch_bounds__(256) void fusedKernel(const float* __restrict__ labels,
                                                   const float* __restrict__ images,
                                                   const float* __restrict__ preds,
                                                   float* __restrict__ out) {
    const int b = blockIdx.y, strip = blockIdx.x;
    const int row0 = strip * ROWS;
    const int tid = threadIdx.x, lane = tid & 31, warp = tid >> 5;

    __shared__ unsigned lw[NLW];
    __shared__ unsigned hwv[NLW];
    __shared__ unsigned stage[CAP];              // reused as scratch in elected tail
    __shared__ unsigned sh_h2[512];
    __shared__ float    sh_cp[256];
    __shared__ unsigned s_n;
    __shared__ unsigned wcnt[8];
    __shared__ float    wp2[8];
    __shared__ unsigned s_rank, s_rank2;
    __shared__ float    s_total, s_p2;
    __shared__ int      s_k1, s_k2;
    __shared__ unsigned long long wkey[8];

    sh_h2[tid] = 0u; sh_h2[tid + 256] = 0u; sh_cp[tid] = 0.0f;
    if (tid == 0) s_n = 0u;
    __syncthreads();

    // ---- phase A: pack label bits — coalesced loads, 8-lane OR-reduce assembly ----
    const float4* lab4 = (const float4*)labels + (size_t)b * G4PB;
    const unsigned mask8 = 0xFFu << (lane & 24);
    #pragma unroll
    for (int it = 0; it < NGH / 256; it++) {
        int gi = it * 256 + tid;
        int r = gi >> 7, c4 = gi & 127;
        int grow = row0 - 2 + r;
        unsigned nib = 0u;
        if (grow >= 0 && grow < HW) {
            float4 v = __ldg(lab4 + grow * 128 + c4);
            nib = (unsigned)(v.x > 0.0f) | ((unsigned)(v.y > 0.0f) << 1)
                | ((unsigned)(v.z > 0.0f) << 2) | ((unsigned)(v.w > 0.0f) << 3);
        }
        unsigned word = __reduce_or_sync(mask8, nib << (4 * (lane & 7)));
        if ((lane & 7) == 0) lw[gi >> 3] = word;
    }
    __syncthreads();

    // ---- phase B: horizontal dilation radius 2 ----
    for (int w = tid; w < NLW; w += 256) {
        int wc = w & 15;
        unsigned C = lw[w];
        unsigned L = wc ? lw[w - 1] : 0u;
        unsigned R = (wc < 15) ? lw[w + 1] : 0u;
        hwv[w] = C | (C << 1) | (C << 2) | (C >> 1) | (C >> 2)
               | (L >> 31) | (L >> 30) | (R << 31) | (R << 30);
    }
    __syncthreads();

    // ---- phase C: vertical OR + count + warp-aggregated staging ----
    {
        int w = tid;
        int r = w >> 4, wc = w & 15;
        unsigned m = hwv[w] | hwv[w + 16] | hwv[w + 32] | hwv[w + 48] | hwv[w + 64];
        unsigned cnt = __popc(m);

        unsigned nz = 0;
        #pragma unroll
        for (int k = 0; k < 8; k++) if ((m >> (k * 4)) & 0xFu) nz |= 1u << k;
        unsigned ne = __popc(nz);

        unsigned off = ne;
        #pragma unroll
        for (int o = 1; o < 32; o <<= 1) {
            unsigned v = __shfl_up_sync(0xffffffffu, off, o);
            if (lane >= o) off += v;
        }
        unsigned tot = __shfl_sync(0xffffffffu, off, 31);
        unsigned exc = off - ne;
        unsigned base = 0;
        if (lane == 31) base = atomicAdd(&s_n, tot);
        base = __shfl_sync(0xffffffffu, base, 31);

        unsigned gw8 = ((row0 + r) * WPR + wc) * 8;
        unsigned pos = base + exc;
        #pragma unroll
        for (int k = 0; k < 8; k++) if (nz & (1u << k)) {
            unsigned nib = (m >> (k * 4)) & 0xFu;
            stage[pos++] = (nib << 16) | (gw8 + k);
        }

        #pragma unroll
        for (int o = 16; o; o >>= 1) cnt += __shfl_down_sync(0xffffffffu, cnt, o);
        if (lane == 0) wcnt[warp] = cnt;
    }
    __syncthreads();

    // ---- phase D: gather img+pred, 2 shared atomics per masked pixel + p^2 register ----
    const unsigned n = s_n;
    const float4* img4 = (const float4*)images + (size_t)b * G4PB;
    const float4* prd4 = (const float4*)preds  + (size_t)b * G4PB;
    const float SCALEF = 256.0f / 255.0f;
    float p2acc = 0.0f;
    for (unsigned i = tid; i < n; i += 256) {
        unsigned e = stage[i];
        unsigned g = e & 0xFFFFu, nib = e >> 16;
        float4 iv = __ldg(img4 + g);
        float4 pv = __ldg(prd4 + g);
        float is[4] = {iv.x, iv.y, iv.z, iv.w};
        float ps[4] = {pv.x, pv.y, pv.z, pv.w};
        #pragma unroll
        for (int k = 0; k < 4; k++) if (nib & (1u << k)) {
            float v255 = is[k] * 255.0f;
            int idx = (int)floorf(v255 * SCALEF);          // otsu bin (reference arithmetic)
            idx = idx < 0 ? 0 : (idx > 255 ? 255 : idx);
            int j = (int)floorf(v255);                     // class bin
            j = j < 0 ? 0 : (j > 255 ? 255 : j);
            int hi = idx - j;                              // 0 or 1, exact
            float p = ps[k];
            atomicAdd(&sh_h2[2 * j + hi], 1u);
            atomicAdd(&sh_cp[j], p);
            p2acc = fmaf(p, p, p2acc);
        }
    }
    #pragma unroll
    for (int o = 16; o; o >>= 1) p2acc += __shfl_down_sync(0xffffffffu, p2acc, o);
    if (lane == 0) wp2[warp] = p2acc;
    __syncthreads();

    // ---- store per-strip partials ----
    g_h2p[b][strip][tid]       = sh_h2[tid];
    g_h2p[b][strip][tid + 256] = sh_h2[tid + 256];
    g_cpp[b][strip][tid]       = sh_cp[tid];
    if (tid == 0) {
        unsigned t = 0; float pp = 0.0f;
        #pragma unroll
        for (int i = 0; i < 8; i++) { t += wcnt[i]; pp += wp2[i]; }
        g_cntp[b][strip] = t;
        g_p2p[b][strip] = pp;
    }

    // ---- election 1: last strip-block of this batch runs the whole per-batch tail ----
    __threadfence();
    __syncthreads();
    if (tid == 0) s_rank = atomicInc(&g_done1[b], NSTR - 1);   // wraps -> replay safe
    __syncthreads();
    if (s_rank != NSTR - 1) return;
    if (tid == 0) __threadfence();
    __syncthreads();

    // ---- tail: merge + scan + prep (all in shared, aliased onto stage) ----
    unsigned* h2m = stage;                       // 512
    float* aS   = (float*)(stage + 512);         // 256
    float* cmvS = (float*)(stage + 768);         // 256
    float* t2S  = (float*)(stage + 1024);        // 256
    unsigned* w2S = stage + 1280;                // 256
    float* ccS  = (float*)(stage + 1536);        // 256
    float* cpS  = (float*)(stage + 1792);        // 256

    {
        unsigned ha = 0, hb = 0; float cpm = 0.0f;
        #pragma unroll
        for (int s = 0; s < NSTR; s++) {
            ha  += g_h2p[b][s][tid];
            hb  += g_h2p[b][s][tid + 256];
            cpm += g_cpp[b][s][tid];
        }
        h2m[tid] = ha; h2m[tid + 256] = hb;
        if (tid == 0) {
            unsigned t = 0; float pp = 0.0f;
            #pragma unroll
            for (int s = 0; s < NSTR; s++) { t += g_cntp[b][s]; pp += g_p2p[b][s]; }
            s_total = (float)t;
            s_p2 = pp;
        }
        __syncthreads();

        ccS[tid] = (float)(h2m[2 * tid] + h2m[2 * tid + 1]);   // class-bin count
        cpS[tid] = cpm;                                         // class-bin sum(p)
        unsigned oh = h2m[2 * tid] + (tid ? h2m[2 * tid - 1] : 0u);  // otsu hist
        float hv = (float)oh / s_total;
        aS[tid] = hv;
        cmvS[tid] = hv * (float)tid;
        __syncthreads();

        // Kogge-Stone inclusive scan
        #pragma unroll
        for (int o = 1; o < 256; o <<= 1) {
            float va = 0.0f, vc = 0.0f;
            if (tid >= o) { va = aS[tid - o]; vc = cmvS[tid - o]; }
            __syncthreads();
            if (tid >= o) { aS[tid] += va; cmvS[tid] += vc; }
            __syncthreads();
        }
    }

    const float tm = cmvS[255];
    const float s = 1e-8f;
    {
        float cb = aS[tid], w2 = 1.0f - cb;
        float mean2 = (tm - cmvS[tid]) / (w2 + s);
        float d2 = mean2 - tm;
        t2S[tid] = w2 * (d2 * d2);
        w2S[tid] = w2 > 0.0f ? 1u : 0u;
    }
    __syncthreads();

    // ---- full search: thread tid owns i=tid; j loop = warp-uniform broadcast LDS ----
    unsigned long long key = 0ull;
    if (tid < NTHR) {
        const int i = tid;
        float w0 = aS[i], m0 = cmvS[i];
        float mean0 = m0 / (w0 + s);             // precise, once per thread
        float d0 = mean0 - tm;
        float term0 = w0 * (d0 * d0);
        bool p0 = w0 > 0.0f;
        float best = -1.0f; int bflat = 0x7fffffff;
        #pragma unroll 4
        for (int j = 0; j < NTHR; j++) {
            float w1 = aS[j] - w0;
            float mean1 = __fdividef(cmvS[j] - m0, w1 + s);
            float d1 = mean1 - tm;
            float bv = term0 + w1 * (d1 * d1) + t2S[j];
            bv = (p0 && w1 > 0.0f && w2S[j]) ? bv : 0.0f;
            if (bv > best) { best = bv; bflat = i * NTHR + j; }   // first max (j asc)
        }
        if (best < 0.0f) best = 0.0f;
        key = ((unsigned long long)__float_as_uint(best) << 32)
            | (unsigned long long)(0x7FFFFFFFu - (unsigned)bflat);
    }
    #pragma unroll
    for (int o = 16; o; o >>= 1) {
        unsigned long long k2 = __shfl_down_sync(0xffffffffu, key, o);
        if (k2 > key) key = k2;
    }
    if (lane == 0) wkey[warp] = key;
    __syncthreads();
    if (tid == 0) {
        unsigned long long k = wkey[0];
        #pragma unroll
        for (int w = 1; w < 8; w++) if (wkey[w] > k) k = wkey[w];
        int am = (int)(0x7FFFFFFFu - (unsigned)(k & 0xFFFFFFFFu));
        s_k1 = am / NTHR + 1;                    // im >= t1 <=> j >= k1
        s_k2 = am % NTHR + 1;
    }
    __syncthreads();

    // ---- closed-form loss for batch b ----
    {
        float cc = ccS[tid];
        float cp = cpS[tid];
        float term = 0.0f;
        if (tid >= s_k2)      term = cc - 2.0f * cp;     // (1-p)^2 minus p^2 part
        else if (tid >= s_k1) term = 0.25f * cc - cp;    // (0.5-p)^2 minus p^2 part
        float* red = aS;                                 // search done; alias
        __syncthreads();
        red[tid] = term;
        __syncthreads();
        for (int st = 128; st; st >>= 1) {
            if (tid < st) red[tid] += red[tid + st];
            __syncthreads();
        }
        if (tid == 0) {
            float sq = red[0] + s_p2;
            float sm = s_total + 1e-8f;
            bool valid = sm > 1e-8f;
            g_lossper[b] = valid ? (sq / sm) : 0.0f;
            g_validb[b] = valid ? 1 : 0;
        }
    }

    // ---- election 2: among 32 batch-elected blocks, last writes the scalar ----
    __threadfence();
    __syncthreads();
    if (tid == 0) s_rank2 = atomicInc(&g_done3, BATCH - 1);    // wraps -> replay safe
    __syncthreads();
    if (s_rank2 != BATCH - 1) return;
    if (tid == 0) __threadfence();
    __syncthreads();

    if (tid < 32) {
        float lp = __ldcg(&g_lossper[tid]);
        int   c  = __ldcg(&g_validb[tid]);
        #pragma unroll
        for (int o = 16; o; o >>= 1) {
            lp += __shfl_down_sync(0xffffffffu, lp, o);
            c  += __shfl_down_sync(0xffffffffu, c, o);
        }
        if (tid == 0) out[0] = (c > 0) ? (lp / (float)(c > 1 ? c : 1)) : 0.0f;
    }
}

// ---------------- launch ----------------
extern "C" void kernel_launch(void* const* d_in, const int* in_sizes, int n_in,
                              void* d_out, int out_size) {
    const float* preds  = (const float*)d_in[0];
    const float* labels = (const float*)d_in[1];
    const float* images = (const float*)d_in[2];
    float* out = (float*)d_out;
    (void)in_sizes; (void)n_in; (void)out_size;

    fusedKernel<<<dim3(NSTR, BATCH), 256>>>(labels, images, preds, out);
}

// round 17
// speedup vs baseline: 1.6885x; 1.6885x over previous
#include <cuda_runtime.h>
#include <cuda_bf16.h>
#include <math.h>

#define BATCH 32
#define HW    512
#define NPIX  (HW*HW)            // 262144
#define WPR   16                 // 32-bit words per row
#define G4PB  (NPIX/4)           // 65536 float4 groups per batch
#define NTHR  254

#define ROWS  16                 // rows per strip
#define NSTR  (HW/ROWS)          // 32 strips
#define HALO  (ROWS+4)           // 20
#define NLW   (HALO*WPR)         // 320 halo words
#define NGH   (HALO*128)         // 2560 halo float4-groups
#define SW    (ROWS*WPR)         // 256 strip words (== blockDim)
#define CAP   (SW*8)             // 2048 staged entries max

#define NCH   8                  // search chunks per batch (32 i's each: 4 per warp)

// ---------------- device scratch (overwrite-style; counters self-reset via wrap) ----------------
__device__ unsigned g_h2p [BATCH][NSTR][512];    // combined hist partials: bin=2j+hi
__device__ float    g_cpp [BATCH][NSTR][256];    // class-bin sum(p) partials
__device__ float    g_p2p [BATCH][NSTR];         // sum(p^2) partials
__device__ unsigned g_cntp[BATCH][NSTR];         // mask-count partials
// merged per-batch (written by K1 elected blocks)
__device__ float    g_a    [BATCH][256];
__device__ float    g_cmv  [BATCH][256];
__device__ float    g_term2[BATCH][256];
__device__ unsigned g_w2p  [BATCH][256];
__device__ unsigned g_ccm  [BATCH][256];         // merged class-bin counts
__device__ float    g_cpm  [BATCH][256];         // merged class-bin sum(p)
__device__ float    g_p2   [BATCH];
__device__ float    g_total[BATCH];
__device__ unsigned long long g_amax[BATCH];
__device__ float    g_lossper[BATCH];
__device__ int      g_validb[BATCH];
__device__ unsigned g_done1[BATCH];              // wraps 0..NSTR-1
__device__ unsigned g_done2[BATCH];              // wraps 0..NCH-1
__device__ unsigned g_done3;                     // wraps 0..BATCH-1

// ======== K1: pack + dilate + stage + gather + 2 histograms + elected per-batch Otsu prep ========
__global__ __launch_bounds__(256) void fusedKernel(const float* __restrict__ labels,
                                                   const float* __restrict__ images,
                                                   const float* __restrict__ preds) {
    const int b = blockIdx.y, strip = blockIdx.x;
    const int row0 = strip * ROWS;
    const int tid = threadIdx.x, lane = tid & 31, warp = tid >> 5;

    __shared__ unsigned lw[NLW];
    __shared__ unsigned hwv[NLW];
    __shared__ unsigned stage[CAP];              // reused as merge scratch in elected tail
    __shared__ unsigned sh_h2[512];
    __shared__ float    sh_cp[256];
    __shared__ unsigned s_n;
    __shared__ unsigned wcnt[8];
    __shared__ float    wp2[8];
    __shared__ unsigned s_rank;

    sh_h2[tid] = 0u; sh_h2[tid + 256] = 0u; sh_cp[tid] = 0.0f;
    if (tid == 0) s_n = 0u;
    if (strip == 0 && tid == 0) g_amax[b] = 0ull;   // reset before K2 (kernel boundary orders it)
    __syncthreads();

    // ---- phase A: pack label bits — coalesced loads, 8-lane OR-reduce assembly ----
    const float4* lab4 = (const float4*)labels + (size_t)b * G4PB;
    const unsigned mask8 = 0xFFu << (lane & 24);
    #pragma unroll
    for (int it = 0; it < NGH / 256; it++) {
        int gi = it * 256 + tid;
        int r = gi >> 7, c4 = gi & 127;
        int grow = row0 - 2 + r;
        unsigned nib = 0u;
        if (grow >= 0 && grow < HW) {
            float4 v = __ldg(lab4 + grow * 128 + c4);
            nib = (unsigned)(v.x > 0.0f) | ((unsigned)(v.y > 0.0f) << 1)
                | ((unsigned)(v.z > 0.0f) << 2) | ((unsigned)(v.w > 0.0f) << 3);
        }
        unsigned word = __reduce_or_sync(mask8, nib << (4 * (lane & 7)));
        if ((lane & 7) == 0) lw[gi >> 3] = word;
    }
    __syncthreads();

    // ---- phase B: horizontal dilation radius 2 ----
    for (int w = tid; w < NLW; w += 256) {
        int wc = w & 15;
        unsigned C = lw[w];
        unsigned L = wc ? lw[w - 1] : 0u;
        unsigned R = (wc < 15) ? lw[w + 1] : 0u;
        hwv[w] = C | (C << 1) | (C << 2) | (C >> 1) | (C >> 2)
               | (L >> 31) | (L >> 30) | (R << 31) | (R << 30);
    }
    __syncthreads();

    // ---- phase C: vertical OR + count + warp-aggregated staging (1 word/thread) ----
    {
        int w = tid;
        int r = w >> 4, wc = w & 15;
        unsigned m = hwv[w] | hwv[w + 16] | hwv[w + 32] | hwv[w + 48] | hwv[w + 64];
        unsigned cnt = __popc(m);

        unsigned nz = 0;
        #pragma unroll
        for (int k = 0; k < 8; k++) if ((m >> (k * 4)) & 0xFu) nz |= 1u << k;
        unsigned ne = __popc(nz);

        unsigned off = ne;
        #pragma unroll
        for (int o = 1; o < 32; o <<= 1) {
            unsigned v = __shfl_up_sync(0xffffffffu, off, o);
            if (lane >= o) off += v;
        }
        unsigned tot = __shfl_sync(0xffffffffu, off, 31);
        unsigned exc = off - ne;
        unsigned base = 0;
        if (lane == 31) base = atomicAdd(&s_n, tot);
        base = __shfl_sync(0xffffffffu, base, 31);

        unsigned gw8 = ((row0 + r) * WPR + wc) * 8;
        unsigned pos = base + exc;
        #pragma unroll
        for (int k = 0; k < 8; k++) if (nz & (1u << k)) {
            unsigned nib = (m >> (k * 4)) & 0xFu;
            stage[pos++] = (nib << 16) | (gw8 + k);
        }

        #pragma unroll
        for (int o = 16; o; o >>= 1) cnt += __shfl_down_sync(0xffffffffu, cnt, o);
        if (lane == 0) wcnt[warp] = cnt;
    }
    __syncthreads();

    // ---- phase D: gather img+pred, 2 shared atomics per masked pixel + p^2 in register ----
    const unsigned n = s_n;
    const float4* img4 = (const float4*)images + (size_t)b * G4PB;
    const float4* prd4 = (const float4*)preds  + (size_t)b * G4PB;
    const float SCALEF = 256.0f / 255.0f;
    float p2acc = 0.0f;
    for (unsigned i = tid; i < n; i += 256) {
        unsigned e = stage[i];
        unsigned g = e & 0xFFFFu, nib = e >> 16;
        float4 iv = __ldg(img4 + g);
        float4 pv = __ldg(prd4 + g);
        float is[4] = {iv.x, iv.y, iv.z, iv.w};
        float ps[4] = {pv.x, pv.y, pv.z, pv.w};
        #pragma unroll
        for (int k = 0; k < 4; k++) if (nib & (1u << k)) {
            float v255 = is[k] * 255.0f;
            int idx = (int)floorf(v255 * SCALEF);          // otsu bin (reference arithmetic)
            idx = idx < 0 ? 0 : (idx > 255 ? 255 : idx);
            int j = (int)floorf(v255);                     // class bin
            j = j < 0 ? 0 : (j > 255 ? 255 : j);
            int hi = idx - j;                              // 0 or 1, exact
            float p = ps[k];
            atomicAdd(&sh_h2[2 * j + hi], 1u);
            atomicAdd(&sh_cp[j], p);
            p2acc = fmaf(p, p, p2acc);
        }
    }
    #pragma unroll
    for (int o = 16; o; o >>= 1) p2acc += __shfl_down_sync(0xffffffffu, p2acc, o);
    if (lane == 0) wp2[warp] = p2acc;
    __syncthreads();

    // ---- store per-strip partials ----
    g_h2p[b][strip][tid]       = sh_h2[tid];
    g_h2p[b][strip][tid + 256] = sh_h2[tid + 256];
    g_cpp[b][strip][tid]       = sh_cp[tid];
    if (tid == 0) {
        unsigned t = 0; float pp = 0.0f;
        #pragma unroll
        for (int i = 0; i < 8; i++) { t += wcnt[i]; pp += wp2[i]; }
        g_cntp[b][strip] = t;
        g_p2p[b][strip] = pp;
    }

    // ---- election: last strip-block of this batch preps Otsu arrays ----
    __threadfence();
    __syncthreads();
    if (tid == 0) s_rank = atomicInc(&g_done1[b], NSTR - 1);   // wraps -> replay safe
    __syncthreads();
    if (s_rank != NSTR - 1) return;
    if (tid == 0) __threadfence();
    __syncthreads();

    {
        unsigned* h2m = stage;                    // 512
        float* a   = (float*)(stage + 512);       // 256
        float* cmv = (float*)(stage + 768);       // 256
        __shared__ float s_total;

        unsigned ha = 0, hb = 0; float cpm = 0.0f;
        #pragma unroll
        for (int s = 0; s < NSTR; s++) {
            ha  += g_h2p[b][s][tid];
            hb  += g_h2p[b][s][tid + 256];
            cpm += g_cpp[b][s][tid];
        }
        h2m[tid] = ha; h2m[tid + 256] = hb;
        if (tid == 0) {
            unsigned t = 0; float pp = 0.0f;
            #pragma unroll
            for (int s = 0; s < NSTR; s++) { t += g_cntp[b][s]; pp += g_p2p[b][s]; }
            s_total = (float)t;
            g_total[b] = (float)t;
            g_p2[b] = pp;
        }
        __syncthreads();

        // merged class count + sum(p) for the loss stage
        unsigned ccj = h2m[2 * tid] + h2m[2 * tid + 1];
        g_ccm[b][tid] = ccj;
        g_cpm[b][tid] = cpm;

        // otsu hist: otsu[t] = h2m[2t] + h2m[2t-1]
        unsigned oh = h2m[2 * tid] + (tid ? h2m[2 * tid - 1] : 0u);
        float hv = (float)oh / s_total;
        __syncthreads();
        a[tid] = hv;
        cmv[tid] = hv * (float)tid;
        __syncthreads();

        // Kogge-Stone inclusive scan
        #pragma unroll
        for (int o = 1; o < 256; o <<= 1) {
            float va = 0.0f, vc = 0.0f;
            if (tid >= o) { va = a[tid - o]; vc = cmv[tid - o]; }
            __syncthreads();
            if (tid >= o) { a[tid] += va; cmv[tid] += vc; }
            __syncthreads();
        }

        const float tm = cmv[255];
        const float s = 1e-8f;
        float cb = a[tid], w2 = 1.0f - cb;
        float mean2 = (tm - cmv[tid]) / (w2 + s);
        float d2 = mean2 - tm;
        g_a[b][tid]     = a[tid];
        g_cmv[b][tid]   = cmv[tid];
        g_term2[b][tid] = w2 * (d2 * d2);
        g_w2p[b][tid]   = w2 > 0.0f ? 1u : 0u;
    }
}

// ======== K2: Otsu search, 4 i's per warp, lane-per-j (conflict-free LDS) + elected tail ========
__global__ __launch_bounds__(256) void otsuSearchKernel(float* __restrict__ out) {
    const int b = blockIdx.y, chunk = blockIdx.x, tid = threadIdx.x;
    const int lane = tid & 31, warp = tid >> 5;

    __shared__ float a[256], cmv[256], term2[256];
    __shared__ unsigned w2p[256];
    __shared__ unsigned long long wkey[8];
    __shared__ unsigned s_rank, s_rank2;

    a[tid]     = g_a[b][tid];
    cmv[tid]   = g_cmv[b][tid];
    term2[tid] = g_term2[b][tid];
    w2p[tid]   = g_w2p[b][tid];
    __syncthreads();

    const float tm = cmv[255];
    const float s = 1e-8f;
    unsigned long long key = 0ull;
    float best = -1.0f; int bflat = 0x7fffffff;
    #pragma unroll
    for (int ii = 0; ii < 4; ii++) {             // 4 i's per warp, ascending
        const int i = chunk * 32 + warp * 4 + ii;
        if (i < NTHR) {
            float w0 = a[i], m0 = cmv[i];        // warp-uniform broadcast LDS
            float mean0 = m0 / (w0 + s);         // precise, once per i
            float d0 = mean0 - tm;
            float term0 = w0 * (d0 * d0);
            bool p0 = w0 > 0.0f;
            #pragma unroll
            for (int t = 0; t < 8; t++) {
                int j = t * 32 + lane;           // consecutive lanes -> conflict-free LDS
                if (j < NTHR) {
                    float w1 = a[j] - w0;
                    float mean1 = __fdividef(cmv[j] - m0, w1 + s);
                    float d1 = mean1 - tm;
                    float bv = term0 + w1 * (d1 * d1) + term2[j];
                    bv = (p0 && w1 > 0.0f && w2p[j]) ? bv : 0.0f;
                    if (bv > best) { best = bv; bflat = i * NTHR + j; }  // (i,j) asc
                }
            }
        }
    }
    if (best < 0.0f) best = 0.0f;
    key = ((unsigned long long)__float_as_uint(best) << 32)
        | (unsigned long long)(0x7FFFFFFFu - (unsigned)bflat);
    #pragma unroll
    for (int o = 16; o; o >>= 1) {
        unsigned long long k2 = __shfl_down_sync(0xffffffffu, key, o);
        if (k2 > key) key = k2;
    }
    if (lane == 0) wkey[warp] = key;
    __syncthreads();

    // ---- election 1: among NCH blocks of this batch ----
    if (tid == 0) {
        unsigned long long k = wkey[0];
        #pragma unroll
        for (int w = 1; w < 8; w++) if (wkey[w] > k) k = wkey[w];
        atomicMax(&g_amax[b], k);
        __threadfence();
        s_rank = atomicInc(&g_done2[b], NCH - 1);       // wraps -> replay safe
    }
    __syncthreads();
    if (s_rank != NCH - 1) return;

    // ---- batch-last block: closed-form loss ----
    __shared__ int s_k1, s_k2;
    if (tid == 0) {
        __threadfence();
        unsigned long long kk = g_amax[b];
        int am = (int)(0x7FFFFFFFu - (unsigned)(kk & 0xFFFFFFFFu));
        s_k1 = am / NTHR + 1;                           // im >= t1 <=> j >= k1
        s_k2 = am % NTHR + 1;
    }
    __syncthreads();

    float cc = (float)g_ccm[b][tid];
    float cp = g_cpm[b][tid];
    float term = 0.0f;
    if (tid >= s_k2)      term = cc - 2.0f * cp;        // (1-p)^2 minus p^2 part
    else if (tid >= s_k1) term = 0.25f * cc - cp;       // (0.5-p)^2 minus p^2 part
    float* red = a;                                     // alias
    __syncthreads();
    red[tid] = term;
    __syncthreads();
    for (int st = 128; st; st >>= 1) {
        if (tid < st) red[tid] += red[tid + st];
        __syncthreads();
    }

    // ---- election 2: among 32 batch-last blocks ----
    if (tid == 0) {
        float sq = red[0] + g_p2[b];
        float sm = g_total[b] + 1e-8f;
        bool valid = sm > 1e-8f;
        g_lossper[b] = valid ? (sq / sm) : 0.0f;
        g_validb[b] = valid ? 1 : 0;
        __threadfence();
        s_rank2 = atomicInc(&g_done3, BATCH - 1);       // wraps -> replay safe
    }
    __syncthreads();
    if (s_rank2 != BATCH - 1) return;

    if (tid < 32) {
        float lp = __ldcg(&g_lossper[tid]);
        int   c  = __ldcg(&g_validb[tid]);
        #pragma unroll
        for (int o = 16; o; o >>= 1) {
            lp += __shfl_down_sync(0xffffffffu, lp, o);
            c  += __shfl_down_sync(0xffffffffu, c, o);
        }
        if (tid == 0) out[0] = (c > 0) ? (lp / (float)(c > 1 ? c : 1)) : 0.0f;
    }
}

// ---------------- launch ----------------
extern "C" void kernel_launch(void* const* d_in, const int* in_sizes, int n_in,
                              void* d_out, int out_size) {
    const float* preds  = (const float*)d_in[0];
    const float* labels = (const float*)d_in[1];
    const float* images = (const float*)d_in[2];
    float* out = (float*)d_out;
    (void)in_sizes; (void)n_in; (void)out_size;

    fusedKernel<<<dim3(NSTR, BATCH), 256>>>(labels, images, preds);
    otsuSearchKernel<<<dim3(NCH, BATCH), 256>>>(out);
}